// round 6
// baseline (speedup 1.0000x reference)
#include <cuda_runtime.h>

#define VOCAB_ 32000
#define B_ 1000
#define T_ 512
#define L_ 25
#define E_ 64
#define H_ 8
#define TICKS (T_ + L_ - 1)        // 536
#define SCALE 2.8853900817779268f  // 2*log2(e), folded into weights for tanh

// vproj[v][j] = (emb[v] @ W_xh0[:,j] + b_h[0][j]) * SCALE   (1 MB, L2-resident)
__device__ float g_vproj[(size_t)VOCAB_ * H_];

typedef unsigned long long ull;

__device__ __forceinline__ void fma2(ull& d, ull a, ull b) {
    asm("fma.rn.f32x2 %0, %1, %2, %0;" : "+l"(d) : "l"(a), "l"(b));
}
__device__ __forceinline__ ull pk(float lo, float hi) {
    ull r; asm("mov.b64 %0, {%1, %2};" : "=l"(r) : "f"(lo), "f"(hi)); return r;
}
__device__ __forceinline__ float2 upk(ull p) {
    float2 r; asm("mov.b64 {%0, %1}, %2;" : "=f"(r.x), "=f"(r.y) : "l"(p)); return r;
}
// input y = 2*log2e * x  ->  tanh(x) = 1 - 2/(2^y + 1)
__device__ __forceinline__ float tanh_scaled(float y) {
    float e; asm("ex2.approx.f32 %0, %1;" : "=f"(e) : "f"(y));
    float r; asm("rcp.approx.f32 %0, %1;" : "=f"(r) : "f"(e + 1.0f));
    return fmaf(r, -2.0f, 1.0f);
}

// -------- Kernel 1: vproj = (emb @ W_xh0 + b_h[0]) * SCALE --------
__global__ void vproj_kernel(const float* __restrict__ emb,
                             const float* __restrict__ W_xh0,
                             const float* __restrict__ b_h) {
    __shared__ float sW[E_ * H_];
    __shared__ float sb[H_];
    for (int i = threadIdx.x; i < E_ * H_; i += blockDim.x) sW[i] = W_xh0[i];
    if (threadIdx.x < H_) sb[threadIdx.x] = b_h[threadIdx.x];
    __syncthreads();

    int v = blockIdx.x * blockDim.x + threadIdx.x;
    if (v >= VOCAB_) return;

    const float4* e4 = (const float4*)(emb + (long)v * E_);
    float acc[H_];
#pragma unroll
    for (int j = 0; j < H_; j++) acc[j] = sb[j];
#pragma unroll
    for (int k4 = 0; k4 < E_ / 4; k4++) {
        float4 ev = e4[k4];
#pragma unroll
        for (int j = 0; j < H_; j++) {
            acc[j] += ev.x * sW[(k4 * 4 + 0) * H_ + j];
            acc[j] += ev.y * sW[(k4 * 4 + 1) * H_ + j];
            acc[j] += ev.z * sW[(k4 * 4 + 2) * H_ + j];
            acc[j] += ev.w * sW[(k4 * 4 + 3) * H_ + j];
        }
    }
    float4* dst = (float4*)(g_vproj + (long)v * H_);
    dst[0] = make_float4(acc[0] * SCALE, acc[1] * SCALE, acc[2] * SCALE, acc[3] * SCALE);
    dst[1] = make_float4(acc[4] * SCALE, acc[5] * SCALE, acc[6] * SCALE, acc[7] * SCALE);
}

// -------- Kernel 2: dual-element warp wavefront --------
// warp handles 2 batch elements; lane l = layer l for both. Weights shared.
// x-rows pre-staged to smem; loop has only LDS + shfl + FFMA2 + MUFU.
__global__ void __launch_bounds__(128, 1) rnn_dual_kernel(
    const int*   __restrict__ x,           // [B, T]
    const float* __restrict__ h0,          // [L, B, H]
    const float* __restrict__ W_xh_rest,   // [L-1, H, H]
    const float* __restrict__ W_hh,        // [L, H, H]
    const float* __restrict__ b_h,         // [L, H]
    const float* __restrict__ W_hy,        // [H, 1]
    const float* __restrict__ b_y,         // [1]
    float* __restrict__ out, int out_size) {

    extern __shared__ ulonglong2 sx[];     // [8 elems][T][2 x 16B] = 128 KB

    const int lane = threadIdx.x & 31;
    const int warp = threadIdx.x >> 5;     // 0..3
    const int bA = blockIdx.x * 8 + warp * 2;
    const int bB = bA + 1;
    const bool act   = (lane < L_);
    const bool hasWx = (lane >= 1) && act;

    // ---- stage scaled x-projection rows for this block's 8 elements ----
    {
        const ulonglong2* vp = (const ulonglong2*)g_vproj;
        for (int q = threadIdx.x; q < 8 * T_; q += 128) {
            int e = q >> 9;                // elem-in-block
            int t = q & (T_ - 1);
            int id = x[(long)(blockIdx.x * 8 + e) * T_ + t];
            sx[q * 2 + 0] = vp[(long)id * 2 + 0];
            sx[q * 2 + 1] = vp[(long)id * 2 + 1];
        }
    }

    // ---- weights in registers, pre-scaled by 2*log2e ----
    ull wxp[32], whhp[32], bp[4];
#pragma unroll
    for (int k = 0; k < 8; k++)
#pragma unroll
        for (int p = 0; p < 4; p++) {
            float a = 0.f, c = 0.f;
            if (hasWx) {
                a = SCALE * W_xh_rest[((lane - 1) * H_ + k) * H_ + 2 * p];
                c = SCALE * W_xh_rest[((lane - 1) * H_ + k) * H_ + 2 * p + 1];
            }
            wxp[k * 4 + p] = pk(a, c);
            float d = 0.f, f = 0.f;
            if (act) {
                d = SCALE * W_hh[(lane * H_ + k) * H_ + 2 * p];
                f = SCALE * W_hh[(lane * H_ + k) * H_ + 2 * p + 1];
            }
            whhp[k * 4 + p] = pk(d, f);
        }
#pragma unroll
    for (int p = 0; p < 4; p++) {
        float a = hasWx ? SCALE * b_h[lane * H_ + 2 * p]     : 0.f;
        float c = hasWx ? SCALE * b_h[lane * H_ + 2 * p + 1] : 0.f;
        bp[p] = pk(a, c);
    }

    // ---- hidden state for both elements (scalars; shfl sources) ----
    float hA[8], hB[8];
#pragma unroll
    for (int k = 0; k < 8; k++) {
        hA[k] = act ? h0[(lane * B_ + bA) * H_ + k] : 0.f;
        hB[k] = act ? h0[(lane * B_ + bB) * H_ + k] : 0.f;
    }

    __syncthreads();

    const ulonglong2* sxA = sx + (warp * 2 + 0) * T_ * 2;
    const ulonglong2* sxB = sx + (warp * 2 + 1) * T_ * 2;

    // prefetch row t=0
    ulonglong2 xA0 = sxA[0], xA1 = sxA[1];
    ulonglong2 xB0 = sxB[0], xB1 = sxB[1];

#pragma unroll 2
    for (int s = 0; s < TICKS; s++) {
        // prefetch next row (uniform LDS broadcast; off the critical path)
        const int tn = (s + 1 < T_) ? (s + 1) : (T_ - 1);
        ulonglong2 pA0 = sxA[tn * 2], pA1 = sxA[tn * 2 + 1];
        ulonglong2 pB0 = sxB[tn * 2], pB1 = sxB[tn * 2 + 1];

        // cross-layer exchange for both elements
        float vA[8], vB[8];
#pragma unroll
        for (int k = 0; k < 8; k++) {
            vA[k] = __shfl_up_sync(0xffffffffu, hA[k], 1);
            vB[k] = __shfl_up_sync(0xffffffffu, hB[k], 1);
        }

        // accumulators: lane 0 from (scaled) x-projection, others from bias
        ull aA0 = (lane == 0) ? xA0.x : bp[0];
        ull aA1 = (lane == 0) ? xA0.y : bp[1];
        ull aA2 = (lane == 0) ? xA1.x : bp[2];
        ull aA3 = (lane == 0) ? xA1.y : bp[3];
        ull aB0 = (lane == 0) ? xB0.x : bp[0];
        ull aB1 = (lane == 0) ? xB0.y : bp[1];
        ull aB2 = (lane == 0) ? xB1.x : bp[2];
        ull aB3 = (lane == 0) ? xB1.y : bp[3];

        // recurrent MACs (independent of shfl results)
#pragma unroll
        for (int k = 0; k < 8; k++) {
            ull dA = pk(hA[k], hA[k]);
            fma2(aA0, dA, whhp[k * 4 + 0]);
            fma2(aA1, dA, whhp[k * 4 + 1]);
            fma2(aA2, dA, whhp[k * 4 + 2]);
            fma2(aA3, dA, whhp[k * 4 + 3]);
            ull dB = pk(hB[k], hB[k]);
            fma2(aB0, dB, whhp[k * 4 + 0]);
            fma2(aB1, dB, whhp[k * 4 + 1]);
            fma2(aB2, dB, whhp[k * 4 + 2]);
            fma2(aB3, dB, whhp[k * 4 + 3]);
        }
        // input MACs (lane 0: wxp == 0)
#pragma unroll
        for (int k = 0; k < 8; k++) {
            ull eA = pk(vA[k], vA[k]);
            fma2(aA0, eA, wxp[k * 4 + 0]);
            fma2(aA1, eA, wxp[k * 4 + 1]);
            fma2(aA2, eA, wxp[k * 4 + 2]);
            fma2(aA3, eA, wxp[k * 4 + 3]);
            ull eB = pk(vB[k], vB[k]);
            fma2(aB0, eB, wxp[k * 4 + 0]);
            fma2(aB1, eB, wxp[k * 4 + 1]);
            fma2(aB2, eB, wxp[k * 4 + 2]);
            fma2(aB3, eB, wxp[k * 4 + 3]);
        }

        // validity window: lane commits only for t = s - lane in [0, T)
        const bool valid = ((unsigned)(s - lane) < (unsigned)T_);

        float2 fA0 = upk(aA0), fA1 = upk(aA1), fA2 = upk(aA2), fA3 = upk(aA3);
        float2 fB0 = upk(aB0), fB1 = upk(aB1), fB2 = upk(aB2), fB3 = upk(aB3);
        float nA0 = tanh_scaled(fA0.x), nA1 = tanh_scaled(fA0.y);
        float nA2 = tanh_scaled(fA1.x), nA3 = tanh_scaled(fA1.y);
        float nA4 = tanh_scaled(fA2.x), nA5 = tanh_scaled(fA2.y);
        float nA6 = tanh_scaled(fA3.x), nA7 = tanh_scaled(fA3.y);
        float nB0 = tanh_scaled(fB0.x), nB1 = tanh_scaled(fB0.y);
        float nB2 = tanh_scaled(fB1.x), nB3 = tanh_scaled(fB1.y);
        float nB4 = tanh_scaled(fB2.x), nB5 = tanh_scaled(fB2.y);
        float nB6 = tanh_scaled(fB3.x), nB7 = tanh_scaled(fB3.y);
        if (valid) {
            hA[0] = nA0; hA[1] = nA1; hA[2] = nA2; hA[3] = nA3;
            hA[4] = nA4; hA[5] = nA5; hA[6] = nA6; hA[7] = nA7;
            hB[0] = nB0; hB[1] = nB1; hB[2] = nB2; hB[3] = nB3;
            hB[4] = nB4; hB[5] = nB5; hB[6] = nB6; hB[7] = nB7;
        }

        xA0 = pA0; xA1 = pA1; xB0 = pB0; xB1 = pB1;
    }

    // ---- outputs ----
    if (act && out_size >= B_ + L_ * B_ * H_) {
#pragma unroll
        for (int k = 0; k < 8; k++) {
            out[B_ + (lane * B_ + bA) * H_ + k] = hA[k];
            out[B_ + (lane * B_ + bB) * H_ + k] = hB[k];
        }
    }
    if (lane == L_ - 1) {
        float sA = b_y[0], sB = b_y[0];
#pragma unroll
        for (int k = 0; k < 8; k++) {
            float w = W_hy[k];
            sA += hA[k] * w;
            sB += hB[k] * w;
        }
        if (bA < out_size) out[bA] = sA;
        if (bB < out_size) out[bB] = sB;
    }
}

extern "C" void kernel_launch(void* const* d_in, const int* in_sizes, int n_in,
                              void* d_out, int out_size) {
    const int*   x          = (const int*)d_in[0];
    const float* h0         = (const float*)d_in[1];
    const float* emb        = (const float*)d_in[2];
    const float* W_xh0      = (const float*)d_in[3];
    const float* W_xh_rest  = (const float*)d_in[4];
    const float* W_hh       = (const float*)d_in[5];
    const float* b_h        = (const float*)d_in[6];
    const float* W_hy       = (const float*)d_in[7];
    const float* b_y        = (const float*)d_in[8];

    vproj_kernel<<<(VOCAB_ + 255) / 256, 256>>>(emb, W_xh0, b_h);

    const int smem_bytes = 8 * T_ * 32;    // 131072
    cudaFuncSetAttribute(rnn_dual_kernel,
                         cudaFuncAttributeMaxDynamicSharedMemorySize, smem_bytes);
    rnn_dual_kernel<<<B_ / 8, 128, smem_bytes>>>(x, h0, W_xh_rest, W_hh, b_h,
                                                 W_hy, b_y, (float*)d_out, out_size);
}

// round 7
// speedup vs baseline: 1.0410x; 1.0410x over previous
#include <cuda_runtime.h>

#define VOCAB_ 32000
#define B_ 1000
#define T_ 512
#define L_ 25
#define E_ 64
#define H_ 8
#define TICKS (T_ + L_ - 1)        // 536
#define SCALE 2.8853900817779268f  // 2*log2(e), folded into weights for tanh

// vproj[v][j] = (emb[v] @ W_xh0[:,j] + b_h[0][j]) * SCALE   (1 MB, L2-resident)
__device__ float g_vproj[(size_t)VOCAB_ * H_];

typedef unsigned long long ull;

__device__ __forceinline__ void fma2(ull& d, ull a, ull b) {
    asm("fma.rn.f32x2 %0, %1, %2, %0;" : "+l"(d) : "l"(a), "l"(b));
}
__device__ __forceinline__ ull pk(float lo, float hi) {
    ull r; asm("mov.b64 %0, {%1, %2};" : "=l"(r) : "f"(lo), "f"(hi)); return r;
}
__device__ __forceinline__ float2 upk(ull p) {
    float2 r; asm("mov.b64 {%0, %1}, %2;" : "=f"(r.x), "=f"(r.y) : "l"(p)); return r;
}
// input y = 2*log2e * x  ->  tanh(x) = 1 - 2/(2^y + 1)
__device__ __forceinline__ float tanh_scaled(float y) {
    float e; asm("ex2.approx.f32 %0, %1;" : "=f"(e) : "f"(y));
    float r; asm("rcp.approx.f32 %0, %1;" : "=f"(r) : "f"(e + 1.0f));
    return fmaf(r, -2.0f, 1.0f);
}

// -------- Kernel 1: vproj = (emb @ W_xh0 + b_h[0]) * SCALE --------
__global__ void vproj_kernel(const float* __restrict__ emb,
                             const float* __restrict__ W_xh0,
                             const float* __restrict__ b_h) {
    __shared__ float sW[E_ * H_];
    __shared__ float sb[H_];
    for (int i = threadIdx.x; i < E_ * H_; i += blockDim.x) sW[i] = W_xh0[i];
    if (threadIdx.x < H_) sb[threadIdx.x] = b_h[threadIdx.x];
    __syncthreads();

    int v = blockIdx.x * blockDim.x + threadIdx.x;
    if (v >= VOCAB_) return;

    const float4* e4 = (const float4*)(emb + (long)v * E_);
    float acc[H_];
#pragma unroll
    for (int j = 0; j < H_; j++) acc[j] = sb[j];
#pragma unroll
    for (int k4 = 0; k4 < E_ / 4; k4++) {
        float4 ev = e4[k4];
#pragma unroll
        for (int j = 0; j < H_; j++) {
            acc[j] += ev.x * sW[(k4 * 4 + 0) * H_ + j];
            acc[j] += ev.y * sW[(k4 * 4 + 1) * H_ + j];
            acc[j] += ev.z * sW[(k4 * 4 + 2) * H_ + j];
            acc[j] += ev.w * sW[(k4 * 4 + 3) * H_ + j];
        }
    }
    float4* dst = (float4*)(g_vproj + (long)v * H_);
    dst[0] = make_float4(acc[0] * SCALE, acc[1] * SCALE, acc[2] * SCALE, acc[3] * SCALE);
    dst[1] = make_float4(acc[4] * SCALE, acc[5] * SCALE, acc[6] * SCALE, acc[7] * SCALE);
}

// ---- one wavefront tick for one element (k-packed MACs, mask-FFMA x-inject) ----
// hp[4]: h pairs (h0,h1)..(h6,h7). wx2/whh2[j*4+p]: weight pairs (W[2p][j],W[2p+1][j]).
// bp[j]: (bias_j, 0). xr: uniform x-row (only lane0's mask=1 uses it).
template<bool GUARD>
__device__ __forceinline__ void elem_tick(
    ull hp[4], const ull* wx2, const ull* whh2, const ull* bp,
    const float* xr, float mask, bool valid) {

    ull vp[4];
#pragma unroll
    for (int p = 0; p < 4; p++) vp[p] = __shfl_up_sync(0xffffffffu, hp[p], 1);

    ull ac[8];
#pragma unroll
    for (int j = 0; j < 8; j++) {
        ac[j] = bp[j];
#pragma unroll
        for (int p = 0; p < 4; p++) fma2(ac[j], hp[p], whh2[j * 4 + p]);
#pragma unroll
        for (int p = 0; p < 4; p++) fma2(ac[j], vp[p], wx2[j * 4 + p]);
    }
    float n[8];
#pragma unroll
    for (int j = 0; j < 8; j++) {
        float2 u = upk(ac[j]);
        float f = fmaf(xr[j], mask, u.x + u.y);
        n[j] = tanh_scaled(f);
    }
    if (GUARD) {
        if (valid) {
#pragma unroll
            for (int p = 0; p < 4; p++) hp[p] = pk(n[2 * p], n[2 * p + 1]);
        }
    } else {
#pragma unroll
        for (int p = 0; p < 4; p++) hp[p] = pk(n[2 * p], n[2 * p + 1]);
    }
}

// -------- Kernel 2: dual-element warp wavefront, k-packed --------
__global__ void __launch_bounds__(128, 1) rnn_kp_kernel(
    const int*   __restrict__ x,           // [B, T]
    const float* __restrict__ h0,          // [L, B, H]
    const float* __restrict__ W_xh_rest,   // [L-1, H, H]
    const float* __restrict__ W_hh,        // [L, H, H]
    const float* __restrict__ b_h,         // [L, H]
    const float* __restrict__ W_hy,        // [H, 1]
    const float* __restrict__ b_y,         // [1]
    float* __restrict__ out, int out_size) {

    extern __shared__ float sx[];          // [8 elems][T][8 floats] = 128 KB

    const int lane = threadIdx.x & 31;
    const int warp = threadIdx.x >> 5;     // 0..3
    const int bA = blockIdx.x * 8 + warp * 2;
    const int bB = bA + 1;
    const bool act   = (lane < L_);
    const bool hasWx = (lane >= 1) && act;
    const float mask = (lane == 0) ? 1.0f : 0.0f;

    // ---- stage scaled x-projection rows for this block's 8 elements ----
    {
        const ulonglong2* vp = (const ulonglong2*)g_vproj;
        ulonglong2* dst = (ulonglong2*)sx;
        for (int q = threadIdx.x; q < 8 * T_; q += 128) {
            int e = q >> 9;
            int t = q & (T_ - 1);
            int id = x[(long)(blockIdx.x * 8 + e) * T_ + t];
            dst[q * 2 + 0] = vp[(long)id * 2 + 0];
            dst[q * 2 + 1] = vp[(long)id * 2 + 1];
        }
    }

    // ---- weights k-packed: pair over k, scalar over j; pre-scaled ----
    ull wx2[32], whh2[32], bp[8];
#pragma unroll
    for (int j = 0; j < 8; j++) {
#pragma unroll
        for (int p = 0; p < 4; p++) {
            float a = 0.f, c = 0.f;
            if (hasWx) {
                a = SCALE * W_xh_rest[((lane - 1) * H_ + 2 * p) * H_ + j];
                c = SCALE * W_xh_rest[((lane - 1) * H_ + 2 * p + 1) * H_ + j];
            }
            wx2[j * 4 + p] = pk(a, c);
            float d = 0.f, f = 0.f;
            if (act) {
                d = SCALE * W_hh[(lane * H_ + 2 * p) * H_ + j];
                f = SCALE * W_hh[(lane * H_ + 2 * p + 1) * H_ + j];
            }
            whh2[j * 4 + p] = pk(d, f);
        }
        bp[j] = pk(hasWx ? SCALE * b_h[lane * H_ + j] : 0.f, 0.f);
    }

    // ---- hidden-state pairs for both elements ----
    ull hpA[4], hpB[4];
#pragma unroll
    for (int p = 0; p < 4; p++) {
        float a0 = act ? h0[(lane * B_ + bA) * H_ + 2 * p]     : 0.f;
        float a1 = act ? h0[(lane * B_ + bA) * H_ + 2 * p + 1] : 0.f;
        hpA[p] = pk(a0, a1);
        float c0 = act ? h0[(lane * B_ + bB) * H_ + 2 * p]     : 0.f;
        float c1 = act ? h0[(lane * B_ + bB) * H_ + 2 * p + 1] : 0.f;
        hpB[p] = pk(c0, c1);
    }

    __syncthreads();

    const float* sxA = sx + (warp * 2 + 0) * T_ * H_;
    const float* sxB = sx + (warp * 2 + 1) * T_ * H_;

    int s = 0;
    // ---- ramp-up: s in [0, L-2], guarded commits ----
#pragma unroll 1
    for (; s < L_ - 1; s++) {
        const bool valid = (s >= lane);
        const float* xrA = sxA + s * H_;
        const float* xrB = sxB + s * H_;
        elem_tick<true>(hpA, wx2, whh2, bp, xrA, mask, valid);
        elem_tick<true>(hpB, wx2, whh2, bp, xrB, mask, valid);
    }
    // ---- steady: s in [L-1, T-1], unconditional commits ----
#pragma unroll 2
    for (; s < T_; s++) {
        const float* xrA = sxA + s * H_;
        const float* xrB = sxB + s * H_;
        elem_tick<false>(hpA, wx2, whh2, bp, xrA, mask, true);
        elem_tick<false>(hpB, wx2, whh2, bp, xrB, mask, true);
    }
    // ---- ramp-down: s in [T, TICKS), guarded (freeze finished lanes) ----
#pragma unroll 1
    for (; s < TICKS; s++) {
        const bool valid = (lane >= s - (T_ - 1));
        const float* xrA = sxA + (T_ - 1) * H_;   // lane0 invalid here; value unused
        const float* xrB = sxB + (T_ - 1) * H_;
        elem_tick<true>(hpA, wx2, whh2, bp, xrA, mask, valid);
        elem_tick<true>(hpB, wx2, whh2, bp, xrB, mask, valid);
    }

    // ---- outputs ----
    if (act && out_size >= B_ + L_ * B_ * H_) {
#pragma unroll
        for (int p = 0; p < 4; p++) {
            float2 uA = upk(hpA[p]);
            out[B_ + (lane * B_ + bA) * H_ + 2 * p]     = uA.x;
            out[B_ + (lane * B_ + bA) * H_ + 2 * p + 1] = uA.y;
            float2 uB = upk(hpB[p]);
            out[B_ + (lane * B_ + bB) * H_ + 2 * p]     = uB.x;
            out[B_ + (lane * B_ + bB) * H_ + 2 * p + 1] = uB.y;
        }
    }
    if (lane == L_ - 1) {
        float sA = b_y[0], sB = b_y[0];
#pragma unroll
        for (int p = 0; p < 4; p++) {
            float2 uA = upk(hpA[p]);
            float2 uB = upk(hpB[p]);
            sA += uA.x * W_hy[2 * p] + uA.y * W_hy[2 * p + 1];
            sB += uB.x * W_hy[2 * p] + uB.y * W_hy[2 * p + 1];
        }
        if (bA < out_size) out[bA] = sA;
        if (bB < out_size) out[bB] = sB;
    }
}

extern "C" void kernel_launch(void* const* d_in, const int* in_sizes, int n_in,
                              void* d_out, int out_size) {
    const int*   x          = (const int*)d_in[0];
    const float* h0         = (const float*)d_in[1];
    const float* emb        = (const float*)d_in[2];
    const float* W_xh0      = (const float*)d_in[3];
    const float* W_xh_rest  = (const float*)d_in[4];
    const float* W_hh       = (const float*)d_in[5];
    const float* b_h        = (const float*)d_in[6];
    const float* W_hy       = (const float*)d_in[7];
    const float* b_y        = (const float*)d_in[8];

    vproj_kernel<<<(VOCAB_ + 255) / 256, 256>>>(emb, W_xh0, b_h);

    const int smem_bytes = 8 * T_ * H_ * 4;    // 131072
    cudaFuncSetAttribute(rnn_kp_kernel,
                         cudaFuncAttributeMaxDynamicSharedMemorySize, smem_bytes);
    rnn_kp_kernel<<<B_ / 8, 128, smem_bytes>>>(x, h0, W_xh_rest, W_hh, b_h,
                                               W_hy, b_y, (float*)d_out, out_size);
}

// round 8
// speedup vs baseline: 1.0849x; 1.0422x over previous
#include <cuda_runtime.h>

#define VOCAB_ 32000
#define B_ 1000
#define T_ 512
#define L_ 25
#define E_ 64
#define H_ 8
#define TICKS (T_ + L_ - 1)        // 536
#define SCALE 2.8853900817779268f  // 2*log2(e), folded into weights for tanh

// vproj[v][j] = (emb[v] @ W_xh0[:,j] + b_h[0][j]) * SCALE   (1 MB, L2-resident)
__device__ float g_vproj[(size_t)VOCAB_ * H_];

typedef unsigned long long ull;

__device__ __forceinline__ void fma2(ull& d, ull a, ull b) {
    asm("fma.rn.f32x2 %0, %1, %2, %0;" : "+l"(d) : "l"(a), "l"(b));
}
__device__ __forceinline__ ull fma2i(ull a, ull b, ull c) {   // d = a*b + c (fresh dst)
    ull d; asm("fma.rn.f32x2 %0, %1, %2, %3;" : "=l"(d) : "l"(a), "l"(b), "l"(c));
    return d;
}
__device__ __forceinline__ ull pk(float lo, float hi) {
    ull r; asm("mov.b64 %0, {%1, %2};" : "=l"(r) : "f"(lo), "f"(hi)); return r;
}
__device__ __forceinline__ float2 upk(ull p) {
    float2 r; asm("mov.b64 {%0, %1}, %2;" : "=f"(r.x), "=f"(r.y) : "l"(p)); return r;
}
// input y = 2*log2e * x  ->  tanh(x) = 1 - 2/(2^y + 1)
__device__ __forceinline__ float tanh_scaled(float y) {
    float e; asm("ex2.approx.f32 %0, %1;" : "=f"(e) : "f"(y));
    float r; asm("rcp.approx.f32 %0, %1;" : "=f"(r) : "f"(e + 1.0f));
    return fmaf(r, -2.0f, 1.0f);
}

// -------- Kernel 1: vproj = (emb @ W_xh0 + b_h[0]) * SCALE --------
__global__ void vproj_kernel(const float* __restrict__ emb,
                             const float* __restrict__ W_xh0,
                             const float* __restrict__ b_h) {
    __shared__ float sW[E_ * H_];
    __shared__ float sb[H_];
    for (int i = threadIdx.x; i < E_ * H_; i += blockDim.x) sW[i] = W_xh0[i];
    if (threadIdx.x < H_) sb[threadIdx.x] = b_h[threadIdx.x];
    __syncthreads();

    int v = blockIdx.x * blockDim.x + threadIdx.x;
    if (v >= VOCAB_) return;

    const float4* e4 = (const float4*)(emb + (long)v * E_);
    float acc[H_];
#pragma unroll
    for (int j = 0; j < H_; j++) acc[j] = sb[j];
#pragma unroll
    for (int k4 = 0; k4 < E_ / 4; k4++) {
        float4 ev = e4[k4];
#pragma unroll
        for (int j = 0; j < H_; j++) {
            acc[j] += ev.x * sW[(k4 * 4 + 0) * H_ + j];
            acc[j] += ev.y * sW[(k4 * 4 + 1) * H_ + j];
            acc[j] += ev.z * sW[(k4 * 4 + 2) * H_ + j];
            acc[j] += ev.w * sW[(k4 * 4 + 3) * H_ + j];
        }
    }
    float4* dst = (float4*)(g_vproj + (long)v * H_);
    dst[0] = make_float4(acc[0] * SCALE, acc[1] * SCALE, acc[2] * SCALE, acc[3] * SCALE);
    dst[1] = make_float4(acc[4] * SCALE, acc[5] * SCALE, acc[6] * SCALE, acc[7] * SCALE);
}

// ---- one wavefront tick. lane0 injects its x-row via identity wx weights. ----
template<bool GUARD>
__device__ __forceinline__ void tick(
    ull hp[4], const ull* wx2, const ull* whh2, const ull* bp,
    ulonglong2 xq0, ulonglong2 xq1, bool lane0, bool valid) {

    ull vp[4];
#pragma unroll
    for (int p = 0; p < 4; p++) vp[p] = __shfl_up_sync(0xffffffffu, hp[p], 1);
    if (lane0) { vp[0] = xq0.x; vp[1] = xq0.y; vp[2] = xq1.x; vp[3] = xq1.y; }

    ull ac[8];
#pragma unroll
    for (int j = 0; j < 8; j++) {
        ac[j] = fma2i(hp[0], whh2[j * 4 + 0], bp[j]);
        fma2(ac[j], hp[1], whh2[j * 4 + 1]);
        fma2(ac[j], hp[2], whh2[j * 4 + 2]);
        fma2(ac[j], hp[3], whh2[j * 4 + 3]);
#pragma unroll
        for (int p = 0; p < 4; p++) fma2(ac[j], vp[p], wx2[j * 4 + p]);
    }
    float n[8];
#pragma unroll
    for (int j = 0; j < 8; j++) {
        float2 u = upk(ac[j]);
        n[j] = tanh_scaled(u.x + u.y);
    }
    if (GUARD) {
        if (valid) {
#pragma unroll
            for (int p = 0; p < 4; p++) hp[p] = pk(n[2 * p], n[2 * p + 1]);
        }
    } else {
#pragma unroll
        for (int p = 0; p < 4; p++) hp[p] = pk(n[2 * p], n[2 * p + 1]);
    }
}

// -------- Kernel 2: warp-per-element wavefront, 8 warps/block (2/SMSP) --------
__global__ void __launch_bounds__(256, 1) rnn_id_kernel(
    const int*   __restrict__ x,           // [B, T]
    const float* __restrict__ h0,          // [L, B, H]
    const float* __restrict__ W_xh_rest,   // [L-1, H, H]
    const float* __restrict__ W_hh,        // [L, H, H]
    const float* __restrict__ b_h,         // [L, H]
    const float* __restrict__ W_hy,        // [H, 1]
    const float* __restrict__ b_y,         // [1]
    float* __restrict__ out, int out_size) {

    extern __shared__ float sx[];          // [8 elems][T][8 floats] = 128 KB

    const int lane = threadIdx.x & 31;
    const int warp = threadIdx.x >> 5;     // 0..7, one elem per warp
    const int b    = blockIdx.x * 8 + warp;
    const bool act   = (lane < L_);
    const bool hasWx = (lane >= 1) && act;
    const bool lane0 = (lane == 0);

    // ---- stage scaled x-projection rows for this block's 8 elements ----
    {
        const ulonglong2* vp = (const ulonglong2*)g_vproj;
        ulonglong2* dst = (ulonglong2*)sx;
        for (int q = threadIdx.x; q < 8 * T_; q += 256) {
            int e = q >> 9;
            int t = q & (T_ - 1);
            int id = x[(long)(blockIdx.x * 8 + e) * T_ + t];
            dst[q * 2 + 0] = vp[(long)id * 2 + 0];
            dst[q * 2 + 1] = vp[(long)id * 2 + 1];
        }
    }

    // ---- weights k-packed (pair over k); lane0 wx = identity (unscaled) ----
    ull wx2[32], whh2[32], bp[8];
#pragma unroll
    for (int j = 0; j < 8; j++) {
#pragma unroll
        for (int p = 0; p < 4; p++) {
            float a, c;
            if (hasWx) {
                a = SCALE * W_xh_rest[((lane - 1) * H_ + 2 * p) * H_ + j];
                c = SCALE * W_xh_rest[((lane - 1) * H_ + 2 * p + 1) * H_ + j];
            } else if (lane0) {
                a = (2 * p     == j) ? 1.0f : 0.0f;   // identity: routes x_j into acc_j
                c = (2 * p + 1 == j) ? 1.0f : 0.0f;
            } else { a = 0.f; c = 0.f; }
            wx2[j * 4 + p] = pk(a, c);
            float d = 0.f, f = 0.f;
            if (act) {
                d = SCALE * W_hh[(lane * H_ + 2 * p) * H_ + j];
                f = SCALE * W_hh[(lane * H_ + 2 * p + 1) * H_ + j];
            }
            whh2[j * 4 + p] = pk(d, f);
        }
        bp[j] = pk(hasWx ? SCALE * b_h[lane * H_ + j] : 0.f, 0.f);
    }

    // ---- hidden-state pairs ----
    ull hp[4];
#pragma unroll
    for (int p = 0; p < 4; p++) {
        float a0 = act ? h0[(lane * B_ + b) * H_ + 2 * p]     : 0.f;
        float a1 = act ? h0[(lane * B_ + b) * H_ + 2 * p + 1] : 0.f;
        hp[p] = pk(a0, a1);
    }

    __syncthreads();

    const ulonglong2* sxe = (const ulonglong2*)(sx + (long)warp * T_ * H_); // 2 per t
    ulonglong2 xq0 = sxe[0], xq1 = sxe[1];

    int s = 0;
    // ---- ramp-up: guarded commits ----
#pragma unroll 1
    for (; s < L_ - 1; s++) {
        int tn = s + 1;
        ulonglong2 p0 = sxe[tn * 2], p1 = sxe[tn * 2 + 1];
        tick<true>(hp, wx2, whh2, bp, xq0, xq1, lane0, s >= lane);
        xq0 = p0; xq1 = p1;
    }
    // ---- steady: unconditional commits ----
#pragma unroll 2
    for (; s < T_; s++) {
        int tn = (s + 1 < T_) ? (s + 1) : (T_ - 1);
        ulonglong2 p0 = sxe[tn * 2], p1 = sxe[tn * 2 + 1];
        tick<false>(hp, wx2, whh2, bp, xq0, xq1, lane0, true);
        xq0 = p0; xq1 = p1;
    }
    // ---- ramp-down: guarded (freeze finished lanes) ----
#pragma unroll 1
    for (; s < TICKS; s++) {
        tick<true>(hp, wx2, whh2, bp, xq0, xq1, lane0, lane >= s - (T_ - 1));
    }

    // ---- outputs ----
    if (act && out_size >= B_ + L_ * B_ * H_) {
#pragma unroll
        for (int p = 0; p < 4; p++) {
            float2 u = upk(hp[p]);
            out[B_ + (lane * B_ + b) * H_ + 2 * p]     = u.x;
            out[B_ + (lane * B_ + b) * H_ + 2 * p + 1] = u.y;
        }
    }
    if (lane == L_ - 1) {
        float sv = b_y[0];
#pragma unroll
        for (int p = 0; p < 4; p++) {
            float2 u = upk(hp[p]);
            sv += u.x * W_hy[2 * p] + u.y * W_hy[2 * p + 1];
        }
        if (b < out_size) out[b] = sv;
    }
}

extern "C" void kernel_launch(void* const* d_in, const int* in_sizes, int n_in,
                              void* d_out, int out_size) {
    const int*   x          = (const int*)d_in[0];
    const float* h0         = (const float*)d_in[1];
    const float* emb        = (const float*)d_in[2];
    const float* W_xh0      = (const float*)d_in[3];
    const float* W_xh_rest  = (const float*)d_in[4];
    const float* W_hh       = (const float*)d_in[5];
    const float* b_h        = (const float*)d_in[6];
    const float* W_hy       = (const float*)d_in[7];
    const float* b_y        = (const float*)d_in[8];

    vproj_kernel<<<(VOCAB_ + 255) / 256, 256>>>(emb, W_xh0, b_h);

    const int smem_bytes = 8 * T_ * H_ * 4;    // 131072
    cudaFuncSetAttribute(rnn_id_kernel,
                         cudaFuncAttributeMaxDynamicSharedMemorySize, smem_bytes);
    rnn_id_kernel<<<B_ / 8, 256, smem_bytes>>>(x, h0, W_xh_rest, W_hh, b_h,
                                               W_hy, b_y, (float*)d_out, out_size);
}

// round 9
// speedup vs baseline: 1.1245x; 1.0365x over previous
#include <cuda_runtime.h>

#define VOCAB_ 32000
#define B_ 1000
#define T_ 512
#define L_ 25
#define E_ 64
#define H_ 8
#define TICKS (T_ + L_ - 1)        // 536
#define SCALE 2.8853900817779268f  // 2*log2(e), folded into weights

// vproj[v][j] = (emb[v] @ W_xh0[:,j] + b_h[0][j]) * SCALE   (1 MB, L2-resident)
__device__ float g_vproj[(size_t)VOCAB_ * H_];

typedef unsigned long long ull;

__device__ __forceinline__ void fma2(ull& d, ull a, ull b) {
    asm("fma.rn.f32x2 %0, %1, %2, %0;" : "+l"(d) : "l"(a), "l"(b));
}
__device__ __forceinline__ ull fma2i(ull a, ull b, ull c) {   // d = a*b + c (fresh dst)
    ull d; asm("fma.rn.f32x2 %0, %1, %2, %3;" : "=l"(d) : "l"(a), "l"(b), "l"(c));
    return d;
}
__device__ __forceinline__ ull pk(float lo, float hi) {
    ull r; asm("mov.b64 %0, {%1, %2};" : "=l"(r) : "f"(lo), "f"(hi)); return r;
}
__device__ __forceinline__ float2 upk(ull p) {
    float2 r; asm("mov.b64 {%0, %1}, %2;" : "=f"(r.x), "=f"(r.y) : "l"(p)); return r;
}
// y = 2*log2e*x (scale pre-folded into weights) -> r = 1/(2^y + 1).  tanh(x) = 1-2r.
__device__ __forceinline__ float rstate(float y) {
    float e; asm("ex2.approx.f32 %0, %1;" : "=f"(e) : "f"(y));
    float r; asm("rcp.approx.f32 %0, %1;" : "=f"(r) : "f"(e + 1.0f));
    return r;
}

// -------- Kernel 1: vproj = (emb @ W_xh0 + b_h[0]) * SCALE --------
__global__ void vproj_kernel(const float* __restrict__ emb,
                             const float* __restrict__ W_xh0,
                             const float* __restrict__ b_h) {
    __shared__ float sW[E_ * H_];
    __shared__ float sb[H_];
    for (int i = threadIdx.x; i < E_ * H_; i += blockDim.x) sW[i] = W_xh0[i];
    if (threadIdx.x < H_) sb[threadIdx.x] = b_h[threadIdx.x];
    __syncthreads();

    int v = blockIdx.x * blockDim.x + threadIdx.x;
    if (v >= VOCAB_) return;

    const float4* e4 = (const float4*)(emb + (long)v * E_);
    float acc[H_];
#pragma unroll
    for (int j = 0; j < H_; j++) acc[j] = sb[j];
#pragma unroll
    for (int k4 = 0; k4 < E_ / 4; k4++) {
        float4 ev = e4[k4];
#pragma unroll
        for (int j = 0; j < H_; j++) {
            acc[j] += ev.x * sW[(k4 * 4 + 0) * H_ + j];
            acc[j] += ev.y * sW[(k4 * 4 + 1) * H_ + j];
            acc[j] += ev.z * sW[(k4 * 4 + 2) * H_ + j];
            acc[j] += ev.w * sW[(k4 * 4 + 3) * H_ + j];
        }
    }
    float4* dst = (float4*)(g_vproj + (long)v * H_);
    dst[0] = make_float4(acc[0] * SCALE, acc[1] * SCALE, acc[2] * SCALE, acc[3] * SCALE);
    dst[1] = make_float4(acc[4] * SCALE, acc[5] * SCALE, acc[6] * SCALE, acc[7] * SCALE);
}

// ---- one wavefront tick (r-state). lane0 injects x via identity wx. ----
template<bool GUARD>
__device__ __forceinline__ void tick(
    ull hp[4], const ull* wx2, const ull* whh2, const ull* bp,
    ulonglong2 xq0, ulonglong2 xq1, bool lane0, bool valid) {

    ull vp[4];
#pragma unroll
    for (int p = 0; p < 4; p++) vp[p] = __shfl_up_sync(0xffffffffu, hp[p], 1);
    if (lane0) { vp[0] = xq0.x; vp[1] = xq0.y; vp[2] = xq1.x; vp[3] = xq1.y; }

    ull ac[8];
#pragma unroll
    for (int j = 0; j < 8; j++) {
        ac[j] = fma2i(hp[0], whh2[j * 4 + 0], bp[j]);
        fma2(ac[j], hp[1], whh2[j * 4 + 1]);
        fma2(ac[j], hp[2], whh2[j * 4 + 2]);
        fma2(ac[j], hp[3], whh2[j * 4 + 3]);
#pragma unroll
        for (int p = 0; p < 4; p++) fma2(ac[j], vp[p], wx2[j * 4 + p]);
    }
    float n[8];
#pragma unroll
    for (int j = 0; j < 8; j++) {
        float2 u = upk(ac[j]);
        n[j] = rstate(u.x + u.y);
    }
    if (GUARD) {
        if (valid) {
#pragma unroll
            for (int p = 0; p < 4; p++) hp[p] = pk(n[2 * p], n[2 * p + 1]);
        }
    } else {
#pragma unroll
        for (int p = 0; p < 4; p++) hp[p] = pk(n[2 * p], n[2 * p + 1]);
    }
}

// -------- Kernel 2: warp-per-element wavefront, r-state, 8 warps/block --------
__global__ void __launch_bounds__(256, 1) rnn_rs_kernel(
    const int*   __restrict__ x,           // [B, T]
    const float* __restrict__ h0,          // [L, B, H]
    const float* __restrict__ W_xh_rest,   // [L-1, H, H]
    const float* __restrict__ W_hh,        // [L, H, H]
    const float* __restrict__ b_h,         // [L, H]
    const float* __restrict__ W_hy,        // [H, 1]
    const float* __restrict__ b_y,         // [1]
    float* __restrict__ out, int out_size) {

    extern __shared__ float sx[];          // [8 elems][T][8 floats] = 128 KB

    const int lane = threadIdx.x & 31;
    const int warp = threadIdx.x >> 5;     // 0..7, one elem per warp
    const int b    = blockIdx.x * 8 + warp;
    const bool act   = (lane < L_);
    const bool hasWx = (lane >= 1) && act;
    const bool lane0 = (lane == 0);

    // ---- stage scaled x-projection rows for this block's 8 elements ----
    {
        const ulonglong2* vp = (const ulonglong2*)g_vproj;
        ulonglong2* dst = (ulonglong2*)sx;
        for (int q = threadIdx.x; q < 8 * T_; q += 256) {
            int e = q >> 9;
            int t = q & (T_ - 1);
            int id = x[(long)(blockIdx.x * 8 + e) * T_ + t];
            dst[q * 2 + 0] = vp[(long)id * 2 + 0];
            dst[q * 2 + 1] = vp[(long)id * 2 + 1];
        }
    }

    // ---- weights, r-state transformed: W' = -2*SCALE*W; bias absorbs sums ----
    // lane0 wx = raw identity (routes the pre-scaled x row straight in).
    ull wx2[32], whh2[32], bp[8];
#pragma unroll
    for (int j = 0; j < 8; j++) {
        float bsum = 0.0f;   // SCALE * (b_j + sum_k Wx[k,j] + sum_k Whh[k,j])
#pragma unroll
        for (int p = 0; p < 4; p++) {
            float a, c;
            if (hasWx) {
                float w0 = W_xh_rest[((lane - 1) * H_ + 2 * p) * H_ + j];
                float w1 = W_xh_rest[((lane - 1) * H_ + 2 * p + 1) * H_ + j];
                a = -2.0f * SCALE * w0;
                c = -2.0f * SCALE * w1;
                bsum += SCALE * (w0 + w1);
            } else if (lane0) {
                a = (2 * p     == j) ? 1.0f : 0.0f;
                c = (2 * p + 1 == j) ? 1.0f : 0.0f;
            } else { a = 0.f; c = 0.f; }
            wx2[j * 4 + p] = pk(a, c);
            float d = 0.f, f = 0.f;
            if (act) {
                float w0 = W_hh[(lane * H_ + 2 * p) * H_ + j];
                float w1 = W_hh[(lane * H_ + 2 * p + 1) * H_ + j];
                d = -2.0f * SCALE * w0;
                f = -2.0f * SCALE * w1;
                bsum += SCALE * (w0 + w1);
            }
            whh2[j * 4 + p] = pk(d, f);
        }
        if (hasWx) bsum += SCALE * b_h[lane * H_ + j];
        bp[j] = pk(bsum, 0.f);
    }

    // ---- hidden state as r-form: r = (1 - h)/2 ----
    ull hp[4];
#pragma unroll
    for (int p = 0; p < 4; p++) {
        float a0 = act ? h0[(lane * B_ + b) * H_ + 2 * p]     : 0.f;
        float a1 = act ? h0[(lane * B_ + b) * H_ + 2 * p + 1] : 0.f;
        hp[p] = pk(0.5f * (1.0f - a0), 0.5f * (1.0f - a1));
    }

    __syncthreads();

    const ulonglong2* sxe = (const ulonglong2*)(sx + (long)warp * T_ * H_); // 2 per t
    ulonglong2 xq0 = sxe[0], xq1 = sxe[1];

    int s = 0;
    // ---- ramp-up: guarded commits ----
#pragma unroll 1
    for (; s < L_ - 1; s++) {
        int tn = s + 1;
        ulonglong2 p0 = sxe[tn * 2], p1 = sxe[tn * 2 + 1];
        tick<true>(hp, wx2, whh2, bp, xq0, xq1, lane0, s >= lane);
        xq0 = p0; xq1 = p1;
    }
    // ---- steady: unconditional commits ----
#pragma unroll 4
    for (; s < T_; s++) {
        int tn = (s + 1 < T_) ? (s + 1) : (T_ - 1);
        ulonglong2 p0 = sxe[tn * 2], p1 = sxe[tn * 2 + 1];
        tick<false>(hp, wx2, whh2, bp, xq0, xq1, lane0, true);
        xq0 = p0; xq1 = p1;
    }
    // ---- ramp-down: guarded (freeze finished lanes) ----
#pragma unroll 1
    for (; s < TICKS; s++) {
        tick<true>(hp, wx2, whh2, bp, xq0, xq1, lane0, lane >= s - (T_ - 1));
    }

    // ---- outputs: convert h = 1 - 2r ----
    if (act && out_size >= B_ + L_ * B_ * H_) {
#pragma unroll
        for (int p = 0; p < 4; p++) {
            float2 u = upk(hp[p]);
            out[B_ + (lane * B_ + b) * H_ + 2 * p]     = fmaf(u.x, -2.0f, 1.0f);
            out[B_ + (lane * B_ + b) * H_ + 2 * p + 1] = fmaf(u.y, -2.0f, 1.0f);
        }
    }
    if (lane == L_ - 1) {
        float sv = b_y[0];
#pragma unroll
        for (int p = 0; p < 4; p++) {
            float2 u = upk(hp[p]);
            sv += fmaf(u.x, -2.0f, 1.0f) * W_hy[2 * p]
                + fmaf(u.y, -2.0f, 1.0f) * W_hy[2 * p + 1];
        }
        if (b < out_size) out[b] = sv;
    }
}

extern "C" void kernel_launch(void* const* d_in, const int* in_sizes, int n_in,
                              void* d_out, int out_size) {
    const int*   x          = (const int*)d_in[0];
    const float* h0         = (const float*)d_in[1];
    const float* emb        = (const float*)d_in[2];
    const float* W_xh0      = (const float*)d_in[3];
    const float* W_xh_rest  = (const float*)d_in[4];
    const float* W_hh       = (const float*)d_in[5];
    const float* b_h        = (const float*)d_in[6];
    const float* W_hy       = (const float*)d_in[7];
    const float* b_y        = (const float*)d_in[8];

    vproj_kernel<<<(VOCAB_ + 255) / 256, 256>>>(emb, W_xh0, b_h);

    const int smem_bytes = 8 * T_ * H_ * 4;    // 131072
    cudaFuncSetAttribute(rnn_rs_kernel,
                         cudaFuncAttributeMaxDynamicSharedMemorySize, smem_bytes);
    rnn_rs_kernel<<<B_ / 8, 256, smem_bytes>>>(x, h0, W_xh_rest, W_hh, b_h,
                                               W_hy, b_y, (float*)d_out, out_size);
}

// round 11
// speedup vs baseline: 1.1592x; 1.0309x over previous
#include <cuda_runtime.h>

#define VOCAB_ 32000
#define B_ 1000
#define T_ 512
#define L_ 25
#define E_ 64
#define H_ 8
#define TICKS (T_ + L_ - 1)        // 536
#define SCALE 2.8853900817779268f  // 2*log2(e), folded into weights

// vproj[v][j] = SCALE*(emb[v]@W_xh0[:,j] + b_h[0][j] + sum_k W_hh[0][k][j])
// The W_hh column-sum is the r-state constant for layer 0 (lane 0's full bias).
__device__ float g_vproj[(size_t)VOCAB_ * H_];

typedef unsigned long long ull;

__device__ __forceinline__ void fma2(ull& d, ull a, ull b) {
    asm("fma.rn.f32x2 %0, %1, %2, %0;" : "+l"(d) : "l"(a), "l"(b));
}
__device__ __forceinline__ ull mul2(ull a, ull b) {           // d = a*b (fresh dst)
    ull d; asm("mul.rn.f32x2 %0, %1, %2;" : "=l"(d) : "l"(a), "l"(b));
    return d;
}
__device__ __forceinline__ ull pk(float lo, float hi) {
    ull r; asm("mov.b64 %0, {%1, %2};" : "=l"(r) : "f"(lo), "f"(hi)); return r;
}
__device__ __forceinline__ float2 upk(ull p) {
    float2 r; asm("mov.b64 {%0, %1}, %2;" : "=f"(r.x), "=f"(r.y) : "l"(p)); return r;
}
// y = 2*log2e*x (scale pre-folded) -> r = 1/(2^y + 1).  tanh(x) = 1 - 2r.
__device__ __forceinline__ float rstate(float y) {
    float e; asm("ex2.approx.f32 %0, %1;" : "=f"(e) : "f"(y));
    float r; asm("rcp.approx.f32 %0, %1;" : "=f"(r) : "f"(e + 1.0f));
    return r;
}

// -------- Kernel 1: vproj (x-proj + layer-0 bias + layer-0 Whh fold) --------
__global__ void vproj_kernel(const float* __restrict__ emb,
                             const float* __restrict__ W_xh0,
                             const float* __restrict__ b_h,
                             const float* __restrict__ W_hh) {
    __shared__ float sW[E_ * H_];
    __shared__ float sb[H_];    // b_h[0][j] + sum_k W_hh[0][k][j]
    for (int i = threadIdx.x; i < E_ * H_; i += blockDim.x) sW[i] = W_xh0[i];
    if (threadIdx.x < H_) {
        int j = threadIdx.x;
        float c = b_h[j];
#pragma unroll
        for (int k = 0; k < H_; k++) c += W_hh[k * H_ + j];   // layer 0 rows
        sb[j] = c;
    }
    __syncthreads();

    int v = blockIdx.x * blockDim.x + threadIdx.x;
    if (v >= VOCAB_) return;

    const float4* e4 = (const float4*)(emb + (long)v * E_);
    float acc[H_];
#pragma unroll
    for (int j = 0; j < H_; j++) acc[j] = sb[j];
#pragma unroll
    for (int k4 = 0; k4 < E_ / 4; k4++) {
        float4 ev = e4[k4];
#pragma unroll
        for (int j = 0; j < H_; j++) {
            acc[j] += ev.x * sW[(k4 * 4 + 0) * H_ + j];
            acc[j] += ev.y * sW[(k4 * 4 + 1) * H_ + j];
            acc[j] += ev.z * sW[(k4 * 4 + 2) * H_ + j];
            acc[j] += ev.w * sW[(k4 * 4 + 3) * H_ + j];
        }
    }
    float4* dst = (float4*)(g_vproj + (long)v * H_);
    dst[0] = make_float4(acc[0] * SCALE, acc[1] * SCALE, acc[2] * SCALE, acc[3] * SCALE);
    dst[1] = make_float4(acc[4] * SCALE, acc[5] * SCALE, acc[6] * SCALE, acc[7] * SCALE);
}

// ---- one wavefront tick (r-state). Per-lane bias row loaded from smem:
// lane0's row is its (fully folded) x-projection for this tick (ptr advances),
// lanes>=1 read their static folded bias. No SELs, no lane-0 special path.
template<bool GUARD>
__device__ __forceinline__ void tick(
    ull hp[4], const ull* wx2, const ull* whh2,
    const float* bptr, bool valid) {

    float4 bq0 = ((const float4*)bptr)[0];
    float4 bq1 = ((const float4*)bptr)[1];

    ull vp[4];
#pragma unroll
    for (int p = 0; p < 4; p++) vp[p] = __shfl_up_sync(0xffffffffu, hp[p], 1);

    ull ac[8];
#pragma unroll
    for (int j = 0; j < 8; j++) {
        ac[j] = mul2(hp[0], whh2[j * 4 + 0]);
        fma2(ac[j], hp[1], whh2[j * 4 + 1]);
        fma2(ac[j], hp[2], whh2[j * 4 + 2]);
        fma2(ac[j], hp[3], whh2[j * 4 + 3]);
#pragma unroll
        for (int p = 0; p < 4; p++) fma2(ac[j], vp[p], wx2[j * 4 + p]);
    }
    const float bb[8] = {bq0.x, bq0.y, bq0.z, bq0.w, bq1.x, bq1.y, bq1.z, bq1.w};
    float n[8];
#pragma unroll
    for (int j = 0; j < 8; j++) {
        float2 u = upk(ac[j]);
        n[j] = rstate((u.x + u.y) + bb[j]);
    }
    if (GUARD) {
        if (valid) {
#pragma unroll
            for (int p = 0; p < 4; p++) hp[p] = pk(n[2 * p], n[2 * p + 1]);
        }
    } else {
#pragma unroll
        for (int p = 0; p < 4; p++) hp[p] = pk(n[2 * p], n[2 * p + 1]);
    }
}

// -------- Kernel 2: warp-per-element wavefront, smem-bias inject --------
__global__ void __launch_bounds__(256, 1) rnn_sb_kernel(
    const int*   __restrict__ x,           // [B, T]
    const float* __restrict__ h0,          // [L, B, H]
    const float* __restrict__ W_xh_rest,   // [L-1, H, H]
    const float* __restrict__ W_hh,        // [L, H, H]
    const float* __restrict__ b_h,         // [L, H]
    const float* __restrict__ W_hy,        // [H, 1]
    const float* __restrict__ b_y,         // [1]
    float* __restrict__ out, int out_size) {

    extern __shared__ float smem[];
    float* sbias = smem;                   // [32][8] static folded biases (1 KB)
    float* sx    = smem + 32 * H_;         // [8 elems][T][8] x rows (128 KB)

    const int lane = threadIdx.x & 31;
    const int warp = threadIdx.x >> 5;     // 0..7, one elem per warp
    const int b    = blockIdx.x * 8 + warp;
    const bool act   = (lane < L_);
    const bool hasWx = (lane >= 1) && act;
    const bool lane0 = (lane == 0);

    // ---- stage scaled x-projection rows for this block's 8 elements ----
    {
        const ulonglong2* vp = (const ulonglong2*)g_vproj;
        ulonglong2* dst = (ulonglong2*)sx;
        for (int q = threadIdx.x; q < 8 * T_; q += 256) {
            int e = q >> 9;
            int t = q & (T_ - 1);
            int id = x[(long)(blockIdx.x * 8 + e) * T_ + t];
            dst[q * 2 + 0] = vp[(long)id * 2 + 0];
            dst[q * 2 + 1] = vp[(long)id * 2 + 1];
        }
    }

    // ---- weights, r-state transformed: W' = -2*SCALE*W; bias absorbs sums ----
    ull wx2[32], whh2[32];
    float bsum[8];
#pragma unroll
    for (int j = 0; j < 8; j++) {
        float bs = 0.0f;   // SCALE * (b_j + sum_k Wx[k,j] + sum_k Whh[k,j])
#pragma unroll
        for (int p = 0; p < 4; p++) {
            float a = 0.f, c = 0.f;
            if (hasWx) {
                float w0 = W_xh_rest[((lane - 1) * H_ + 2 * p) * H_ + j];
                float w1 = W_xh_rest[((lane - 1) * H_ + 2 * p + 1) * H_ + j];
                a = -2.0f * SCALE * w0;
                c = -2.0f * SCALE * w1;
                bs += SCALE * (w0 + w1);
            }
            wx2[j * 4 + p] = pk(a, c);
            float d = 0.f, f = 0.f;
            if (act) {
                float w0 = W_hh[(lane * H_ + 2 * p) * H_ + j];
                float w1 = W_hh[(lane * H_ + 2 * p + 1) * H_ + j];
                d = -2.0f * SCALE * w0;
                f = -2.0f * SCALE * w1;
                bs += SCALE * (w0 + w1);
            }
            whh2[j * 4 + p] = pk(d, f);
        }
        if (hasWx) bs += SCALE * b_h[lane * H_ + j];
        bsum[j] = bs;
    }
    // warp 0 publishes the static per-lane bias rows (lane0 row unused)
    if (warp == 0) {
#pragma unroll
        for (int j = 0; j < 8; j++) sbias[lane * H_ + j] = bsum[j];
    }

    // ---- hidden state as r-form: r = (1 - h)/2 ----
    ull hp[4];
#pragma unroll
    for (int p = 0; p < 4; p++) {
        float a0 = act ? h0[(lane * B_ + b) * H_ + 2 * p]     : 0.f;
        float a1 = act ? h0[(lane * B_ + b) * H_ + 2 * p + 1] : 0.f;
        hp[p] = pk(0.5f * (1.0f - a0), 0.5f * (1.0f - a1));
    }

    __syncthreads();

    // per-lane bias pointer: lane0 walks its x-row stream, others static bias
    const float* bptr = lane0 ? (sx + (long)warp * T_ * H_) : (sbias + lane * H_);
    const long binc = lane0 ? H_ : 0;

    int s = 0;
    // ---- ramp-up: guarded commits ----
#pragma unroll 1
    for (; s < L_ - 1; s++) {
        tick<true>(hp, wx2, whh2, bptr, s >= lane);
        bptr += binc;
    }
    // ---- steady: unconditional commits ----
#pragma unroll 4
    for (; s < T_; s++) {
        tick<false>(hp, wx2, whh2, bptr, true);
        bptr += binc;
    }
    bptr -= binc;   // clamp: lane0 re-reads x(T-1) during ramp-down (unused)
    // ---- ramp-down: guarded (freeze finished lanes) ----
#pragma unroll 1
    for (; s < TICKS; s++) {
        tick<true>(hp, wx2, whh2, bptr, lane >= s - (T_ - 1));
    }

    // ---- outputs: convert h = 1 - 2r ----
    if (act && out_size >= B_ + L_ * B_ * H_) {
#pragma unroll
        for (int p = 0; p < 4; p++) {
            float2 u = upk(hp[p]);
            out[B_ + (lane * B_ + b) * H_ + 2 * p]     = fmaf(u.x, -2.0f, 1.0f);
            out[B_ + (lane * B_ + b) * H_ + 2 * p + 1] = fmaf(u.y, -2.0f, 1.0f);
        }
    }
    if (lane == L_ - 1) {
        float sv = b_y[0];
#pragma unroll
        for (int p = 0; p < 4; p++) {
            float2 u = upk(hp[p]);
            sv += fmaf(u.x, -2.0f, 1.0f) * W_hy[2 * p]
                + fmaf(u.y, -2.0f, 1.0f) * W_hy[2 * p + 1];
        }
        if (b < out_size) out[b] = sv;
    }
}

extern "C" void kernel_launch(void* const* d_in, const int* in_sizes, int n_in,
                              void* d_out, int out_size) {
    const int*   x          = (const int*)d_in[0];
    const float* h0         = (const float*)d_in[1];
    const float* emb        = (const float*)d_in[2];
    const float* W_xh0      = (const float*)d_in[3];
    const float* W_xh_rest  = (const float*)d_in[4];
    const float* W_hh       = (const float*)d_in[5];
    const float* b_h        = (const float*)d_in[6];
    const float* W_hy       = (const float*)d_in[7];
    const float* b_y        = (const float*)d_in[8];

    vproj_kernel<<<(VOCAB_ + 255) / 256, 256>>>(emb, W_xh0, b_h, W_hh);

    const int smem_bytes = (32 * H_ + 8 * T_ * H_) * 4;   // 1 KB + 128 KB
    cudaFuncSetAttribute(rnn_sb_kernel,
                         cudaFuncAttributeMaxDynamicSharedMemorySize, smem_bytes);
    rnn_sb_kernel<<<B_ / 8, 256, smem_bytes>>>(x, h0, W_xh_rest, W_hh, b_h,
                                               W_hy, b_y, (float*)d_out, out_size);
}